// round 4
// baseline (speedup 1.0000x reference)
#include <cuda_runtime.h>

#define GRID     1184      // 148 SMs * 8 blocks (all co-resident; GB300 has 152 SMs)
#define THREADS  256
#define NWARPS   (THREADS / 32)

__device__ float                 g_partials[GRID];
__device__ unsigned int          g_arrive = 0;      // reset by last block each launch
__device__ volatile unsigned int g_gen    = 0;      // monotonic across graph replays
__device__ volatile float        g_inv;

__device__ __forceinline__ float block_reduce(float v, float* warp_sums)
{
    #pragma unroll
    for (int off = 16; off > 0; off >>= 1)
        v += __shfl_xor_sync(0xffffffffu, v, off);
    int lane = threadIdx.x & 31;
    int wid  = threadIdx.x >> 5;
    if (lane == 0) warp_sums[wid] = v;
    __syncthreads();
    float t = 0.0f;
    if (wid == 0) {
        t = (lane < NWARPS) ? warp_sums[lane] : 0.0f;
        #pragma unroll
        for (int off = NWARPS / 2; off > 0; off >>= 1)
            t += __shfl_xor_sync(0xffffffffu, t, off);
    }
    return t;   // valid in warp 0
}

__global__ __launch_bounds__(THREADS, 8) void softmax_persistent_kernel(
    const float4* __restrict__ in, float4* __restrict__ out, int n4)
{
    __shared__ float    warp_sums[NWARPS];
    __shared__ unsigned s_ticket;
    __shared__ unsigned s_gen;

    const int chunk = (n4 + GRID - 1) / GRID;
    const int beg   = blockIdx.x * chunk;
    const int end   = min(beg + chunk, n4);

    // ---------------- phase 1: sum(exp) over own contiguous tile ----------------
    float s = 0.0f;
    int i = beg + threadIdx.x;
    for (; i + 3 * THREADS < end; i += 4 * THREADS) {
        float4 a = in[i];
        float4 b = in[i + THREADS];
        float4 c = in[i + 2 * THREADS];
        float4 d = in[i + 3 * THREADS];
        s += __expf(a.x) + __expf(a.y) + __expf(a.z) + __expf(a.w);
        s += __expf(b.x) + __expf(b.y) + __expf(b.z) + __expf(b.w);
        s += __expf(c.x) + __expf(c.y) + __expf(c.z) + __expf(c.w);
        s += __expf(d.x) + __expf(d.y) + __expf(d.z) + __expf(d.w);
    }
    for (; i < end; i += THREADS) {
        float4 v = in[i];
        s += __expf(v.x) + __expf(v.y) + __expf(v.z) + __expf(v.w);
    }

    float bsum = block_reduce(s, warp_sums);

    // ---------------- grid barrier + global reduce ----------------
    if (threadIdx.x == 0) {
        g_partials[blockIdx.x] = bsum;
        s_gen = g_gen;                       // read BEFORE arriving (gen can't change until all arrive)
        __threadfence();                     // partial visible before ticket
        s_ticket = atomicAdd(&g_arrive, 1u);
    }
    __syncthreads();

    if (s_ticket == GRID - 1) {
        // last block: whole block reduces all partials (fixed order -> deterministic)
        __threadfence();
        float t = 0.0f;
        for (int j = threadIdx.x; j < GRID; j += THREADS)
            t += g_partials[j];
        float total = block_reduce(t, warp_sums);
        if (threadIdx.x == 0) {
            g_inv = 1.0f / total;
            g_arrive = 0;                    // sole writer here; ready for next replay
            __threadfence();                 // g_inv + reset visible before release
            g_gen = s_gen + 1u;              // release
        }
        __syncthreads();
    } else {
        if (threadIdx.x == 0) {
            while (g_gen == s_gen) __nanosleep(64);
        }
        __syncthreads();
        __threadfence();                     // acquire: order g_inv read after gen observation
    }

    const float inv = g_inv;

    // ---------------- phase 2: out = exp(x) * inv over same tile (L2-hot) ----------------
    i = beg + threadIdx.x;
    for (; i + 3 * THREADS < end; i += 4 * THREADS) {
        float4 a = __ldcs(&in[i]);
        float4 b = __ldcs(&in[i + THREADS]);
        float4 c = __ldcs(&in[i + 2 * THREADS]);
        float4 d = __ldcs(&in[i + 3 * THREADS]);
        float4 ra, rb, rc, rd;
        ra.x = __expf(a.x) * inv; ra.y = __expf(a.y) * inv; ra.z = __expf(a.z) * inv; ra.w = __expf(a.w) * inv;
        rb.x = __expf(b.x) * inv; rb.y = __expf(b.y) * inv; rb.z = __expf(b.z) * inv; rb.w = __expf(b.w) * inv;
        rc.x = __expf(c.x) * inv; rc.y = __expf(c.y) * inv; rc.z = __expf(c.z) * inv; rc.w = __expf(c.w) * inv;
        rd.x = __expf(d.x) * inv; rd.y = __expf(d.y) * inv; rd.z = __expf(d.z) * inv; rd.w = __expf(d.w) * inv;
        __stcs(&out[i], ra);
        __stcs(&out[i + THREADS], rb);
        __stcs(&out[i + 2 * THREADS], rc);
        __stcs(&out[i + 3 * THREADS], rd);
    }
    for (; i < end; i += THREADS) {
        float4 v = __ldcs(&in[i]);
        float4 r;
        r.x = __expf(v.x) * inv; r.y = __expf(v.y) * inv;
        r.z = __expf(v.z) * inv; r.w = __expf(v.w) * inv;
        __stcs(&out[i], r);
    }
}

extern "C" void kernel_launch(void* const* d_in, const int* in_sizes, int n_in,
                              void* d_out, int out_size)
{
    const float4* in  = (const float4*)d_in[0];
    float4*       out = (float4*)d_out;
    int n4 = in_sizes[0] >> 2;   // N = 33554432, divisible by 4

    softmax_persistent_kernel<<<GRID, THREADS>>>(in, out, n4);
}

// round 5
// speedup vs baseline: 1.1280x; 1.1280x over previous
#include <cuda_runtime.h>

#define GRID     2048
#define THREADS  256
#define NWARPS   (THREADS / 32)
#define TSTRIDE  (GRID * THREADS)     // 524288 threads; n4 = 8388608 = 16 * TSTRIDE

__device__ float        g_partials[GRID];
__device__ unsigned int g_arrive = 0;   // reset by the sole last block each launch
__device__ float        g_inv;

__device__ __forceinline__ float block_reduce(float v, float* warp_sums)
{
    #pragma unroll
    for (int off = 16; off > 0; off >>= 1)
        v += __shfl_xor_sync(0xffffffffu, v, off);
    int lane = threadIdx.x & 31;
    int wid  = threadIdx.x >> 5;
    if (lane == 0) warp_sums[wid] = v;
    __syncthreads();
    float t = 0.0f;
    if (wid == 0) {
        t = (lane < NWARPS) ? warp_sums[lane] : 0.0f;
        #pragma unroll
        for (int off = NWARPS / 2; off > 0; off >>= 1)
            t += __shfl_xor_sync(0xffffffffu, t, off);
    }
    return t;   // valid in warp 0 lane 0
}

// ---------------- pass 1: sum(exp(x)), forward order, MLP-4 ----------------
__global__ __launch_bounds__(THREADS) void softmax_sum_kernel(
    const float4* __restrict__ in, int n4)
{
    __shared__ float warp_sums[NWARPS];
    const int tid = blockIdx.x * THREADS + threadIdx.x;
    const int K   = n4 / TSTRIDE;

    float s = 0.0f;
    int k = 0;
    for (; k + 4 <= K; k += 4) {
        float4 a = in[tid + (k + 0) * TSTRIDE];
        float4 b = in[tid + (k + 1) * TSTRIDE];
        float4 c = in[tid + (k + 2) * TSTRIDE];
        float4 d = in[tid + (k + 3) * TSTRIDE];
        s += __expf(a.x) + __expf(a.y) + __expf(a.z) + __expf(a.w);
        s += __expf(b.x) + __expf(b.y) + __expf(b.z) + __expf(b.w);
        s += __expf(c.x) + __expf(c.y) + __expf(c.z) + __expf(c.w);
        s += __expf(d.x) + __expf(d.y) + __expf(d.z) + __expf(d.w);
    }
    for (; k < K; k++) {
        float4 v = in[tid + k * TSTRIDE];
        s += __expf(v.x) + __expf(v.y) + __expf(v.z) + __expf(v.w);
    }
    for (int i = K * TSTRIDE + tid; i < n4; i += TSTRIDE) {  // tail (empty for N=32M)
        float4 v = in[i];
        s += __expf(v.x) + __expf(v.y) + __expf(v.z) + __expf(v.w);
    }

    float bsum = block_reduce(s, warp_sums);

    // ticket: sole last-arriving block reduces partials (no one waits on it)
    __shared__ unsigned s_ticket;
    if (threadIdx.x == 0) {
        g_partials[blockIdx.x] = bsum;
        __threadfence();                         // partial visible before ticket
        s_ticket = atomicAdd(&g_arrive, 1u);
    }
    __syncthreads();

    if (s_ticket == GRID - 1) {
        __threadfence();
        float t = 0.0f;
        for (int j = threadIdx.x; j < GRID; j += THREADS)   // fixed order: deterministic
            t += g_partials[j];
        float total = block_reduce(t, warp_sums);
        if (threadIdx.x == 0) {
            g_inv    = 1.0f / total;
            g_arrive = 0;                        // ready for next graph replay
        }
    }
}

// ---------------- pass 2: out = exp(x)/sum, REVERSE order (L2-hot tail first) ----------------
__global__ __launch_bounds__(THREADS) void softmax_scale_kernel(
    const float4* __restrict__ in, float4* __restrict__ out, int n4)
{
    const int   tid = blockIdx.x * THREADS + threadIdx.x;
    const int   K   = n4 / TSTRIDE;
    const float inv = g_inv;

    // tail indices (highest addresses) first — empty for N=32M
    for (int i = K * TSTRIDE + tid; i < n4; i += TSTRIDE) {
        float4 v = __ldcs(&in[i]);
        float4 r;
        r.x = __expf(v.x) * inv; r.y = __expf(v.y) * inv;
        r.z = __expf(v.z) * inv; r.w = __expf(v.w) * inv;
        __stcs(&out[i], r);
    }

    int k = K - 4;
    for (; k >= 0; k -= 4) {
        // highest (most recently cached) addresses first within the batch
        float4 a = __ldcs(&in[tid + (k + 3) * TSTRIDE]);
        float4 b = __ldcs(&in[tid + (k + 2) * TSTRIDE]);
        float4 c = __ldcs(&in[tid + (k + 1) * TSTRIDE]);
        float4 d = __ldcs(&in[tid + (k + 0) * TSTRIDE]);
        float4 ra, rb, rc, rd;
        ra.x = __expf(a.x) * inv; ra.y = __expf(a.y) * inv; ra.z = __expf(a.z) * inv; ra.w = __expf(a.w) * inv;
        rb.x = __expf(b.x) * inv; rb.y = __expf(b.y) * inv; rb.z = __expf(b.z) * inv; rb.w = __expf(b.w) * inv;
        rc.x = __expf(c.x) * inv; rc.y = __expf(c.y) * inv; rc.z = __expf(c.z) * inv; rc.w = __expf(c.w) * inv;
        rd.x = __expf(d.x) * inv; rd.y = __expf(d.y) * inv; rd.z = __expf(d.z) * inv; rd.w = __expf(d.w) * inv;
        __stcs(&out[tid + (k + 3) * TSTRIDE], ra);
        __stcs(&out[tid + (k + 2) * TSTRIDE], rb);
        __stcs(&out[tid + (k + 1) * TSTRIDE], rc);
        __stcs(&out[tid + (k + 0) * TSTRIDE], rd);
    }
    for (k += 3; k >= 0; k--) {   // remainder when K % 4 != 0 (empty for N=32M)
        int i = tid + k * TSTRIDE;
        float4 v = __ldcs(&in[i]);
        float4 r;
        r.x = __expf(v.x) * inv; r.y = __expf(v.y) * inv;
        r.z = __expf(v.z) * inv; r.w = __expf(v.w) * inv;
        __stcs(&out[i], r);
    }
}

extern "C" void kernel_launch(void* const* d_in, const int* in_sizes, int n_in,
                              void* d_out, int out_size)
{
    const float4* in  = (const float4*)d_in[0];
    float4*       out = (float4*)d_out;
    int n4 = in_sizes[0] >> 2;   // N = 33554432, divisible by 4

    softmax_sum_kernel<<<GRID, THREADS>>>(in, n4);
    softmax_scale_kernel<<<GRID, THREADS>>>(in, out, n4);
}